// round 14
// baseline (speedup 1.0000x reference)
#include <cuda_runtime.h>

// GRU: B=2048, T=1024, I=1, H=20.
// d_out layout: [ y (B*T floats, b*T+t) | h_last (B*H floats, b*H+j) ]
//
// R14 = R13 stream (gate-split, 53 fma2/step, 3-op activations, no loop
// syncs) at THREE warps per SMSP: 86 blocks x 12 warps, 1 pair/warp.
// Rationale: ncu shows fma pipe 60% idle + issue 59% idle at 2 warps/SMSP
// -> latency-exposure-bound; a third independent chain per SMSP fills the
// bubbles. Limits honored: 384 thr x 160 regs = 61.4K < 64K RF; CH=8 keeps
// 12 h-rings under the 48KB static smem cap. 86*12=1032 warp-slots cover
// 1024 pairs; surplus slots exit after the init barrier.
// Lane map: l<20: rowA=r_l, rowB=n_l, owns h_l (reg); 20+m: rowA=z_m,
// rowB=z_{m+10}; 30,31 padded. z_j returns via 2 shfl.64 per step.
// sigmoid = 0.5+0.5*tanh (0.5-prescaled weights); 3-op Horner activations.

typedef unsigned long long u64;

#define B_   2048
#define T_   1024
#define H_   20
#define NW   12                // warps per block (3 per SMSP)
#define NTH  (NW * 32)         // 384
#define NPAIR (B_ / 2)         // 1024
#define NBLK ((NPAIR + NW - 1) / NW)   // 86
#define CH   8
#define NCHUNK (T_ / CH)       // 128
#define ROWP 33                // odd row stride (float2) -> conflict-free y-phase

__device__ __forceinline__ u64 pack2(float lo, float hi) {
    u64 r; asm("mov.b64 %0,{%1,%2};" : "=l"(r) : "f"(lo), "f"(hi)); return r;
}
__device__ __forceinline__ u64 dup2(float v) { return pack2(v, v); }
__device__ __forceinline__ void unpack2(u64 a, float& lo, float& hi) {
    asm("mov.b64 {%0,%1},%2;" : "=f"(lo), "=f"(hi) : "l"(a));
}
__device__ __forceinline__ u64 fma2(u64 a, u64 b, u64 c) {
    u64 d; asm("fma.rn.f32x2 %0,%1,%2,%3;" : "=l"(d) : "l"(a), "l"(b), "l"(c)); return d;
}
__device__ __forceinline__ u64 mul2(u64 a, u64 b) {
    u64 d; asm("mul.rn.f32x2 %0,%1,%2;" : "=l"(d) : "l"(a), "l"(b)); return d;
}
__device__ __forceinline__ u64 add2(u64 a, u64 b) {
    u64 d; asm("add.rn.f32x2 %0,%1,%2;" : "=l"(d) : "l"(a), "l"(b)); return d;
}
__device__ __forceinline__ u64 neg2(u64 a) { return a ^ 0x8000000080000000ULL; }

__global__ void __launch_bounds__(NTH, 1)
gru_kernel(const float* __restrict__ X,     // [B, T]
           const float* __restrict__ h0,    // [B, H]
           const float* __restrict__ Wih,   // [3H, 1]
           const float* __restrict__ Whh,   // [3H, H]  rows: r(0..19) z(20..39) n(40..59)
           const float* __restrict__ bih,   // [3H]
           const float* __restrict__ bhh,   // [3H]
           const float* __restrict__ Wout,  // [H]
           const float* __restrict__ bout,  // [1]
           float* __restrict__ out)
{
    __shared__ float2 hbuf[NW][CH + 1][ROWP];   // per-warp h ring + y history
    __shared__ float2 xs[NW][CH];               // per-warp packed X chunk
    __shared__ float  wout_s[H_];
    __shared__ float  bout_s;

    const int w    = threadIdx.x >> 5;
    const int l    = threadIdx.x & 31;
    const int pair = blockIdx.x * NW + w;

    if (threadIdx.x < H_) wout_s[threadIdx.x] = Wout[threadIdx.x];
    if (threadIdx.x == 0) bout_s = bout[0];
    __syncthreads();   // once: publish wout_s/bout_s (all warps participate)

    if (pair >= NPAIR) return;   // surplus warp-slots (last block only)

    const bool lt20 = (l < 20);
    const bool lt30 = (l < 30);
    const int rowA = l;                            // r_l (l<20) or z_{l-20}
    const int rowB = lt20 ? (40 + l) : (l + 10);   // n_l or z_{l-10}
    const int bev  = pair * 2;
    // z-gather source lane for unit j=l (<20): j<10 -> lane 20+j (gA),
    // j>=10 -> lane 10+j = 20+(j-10) (gB). Spares: any valid lane.
    const int zsrc = lt20 ? (l < 10 ? 20 + l : 10 + l) : 20;

    // ---- per-lane packed constants ----
    u64 wA[H_], wB[H_];
#pragma unroll
    for (int k = 0; k < H_; k++) {
        wA[k] = lt30 ? dup2(0.5f * Whh[rowA * H_ + k]) : 0ULL;
        wB[k] = lt30 ? dup2((lt20 ? 1.0f : 0.5f) * Whh[rowB * H_ + k]) : 0ULL;
    }
    const u64 bA0  = lt30 ? dup2(0.5f * (bih[rowA] + bhh[rowA])) : 0ULL;
    const u64 xwA  = lt30 ? dup2(0.5f * Wih[rowA]) : 0ULL;
    const u64 bB0  = lt30 ? (lt20 ? dup2(bhh[rowB])
                                  : dup2(0.5f * (bih[rowB] + bhh[rowB]))) : 0ULL;
    const u64 winB = lt30 ? (lt20 ? dup2(Wih[rowB]) : dup2(0.5f * Wih[rowB])) : 0ULL;
    const u64 binB = (lt30 && lt20) ? dup2(bih[rowB]) : 0ULL;
    const u64 HALF = dup2(0.5f);
    const u64 ONE  = dup2(1.0f);
    // 3-op activation constants
    const u64 CA   = dup2(-1.0f / 6.0f);            // phase A: sigma(2u)
    const u64 C3B  = lt20 ? dup2(-1.0f / 3.0f) : dup2(-1.0f / 6.0f);
    const u64 A1B  = lt20 ? ONE  : HALF;
    const u64 B0B  = lt20 ? 0ULL : HALF;

    // h for owned unit (lanes 0..19) lives in a register
    u64 h2 = lt20 ? pack2(h0[bev * H_ + l], h0[(bev + 1) * H_ + l]) : 0ULL;

    for (int c = 0; c < NCHUNK; c++) {
        const int t0 = c * CH;
        // warp-private smem, convergent warp: per-warp in-order LSU orders
        // these stores before the loads below (no syncwarp needed).
        if (l < CH)           xs[w][l].x      = X[bev * T_ + t0 + l];
        else if (l < 2 * CH)  xs[w][l - CH].y = X[(bev + 1) * T_ + t0 + l - CH];
        *(u64*)&hbuf[w][0][l] = h2;

#pragma unroll
        for (int tc = 0; tc < CH; tc++) {
            // split even/odd-k accumulators (chain depth 10), LDS.64 reads
            u64 accA0 = bA0, accA1 = 0ULL;
            u64 accB0 = bB0, accB1 = 0ULL;
            const u64* hrow = (const u64*)&hbuf[w][tc][0];
#pragma unroll
            for (int kk = 0; kk < H_ / 2; kk++) {   // 20x LDS.64, 40 fma2
                u64 h0v = hrow[2 * kk];
                u64 h1v = hrow[2 * kk + 1];
                accA0 = fma2(wA[2 * kk],     h0v, accA0);
                accB0 = fma2(wB[2 * kk],     h0v, accB0);
                accA1 = fma2(wA[2 * kk + 1], h1v, accA1);
                accB1 = fma2(wB[2 * kk + 1], h1v, accB1);
            }
            u64 x2 = *(const u64*)&xs[w][tc];
            u64 accA = add2(accA0, accA1);
            u64 accB = add2(accB0, accB1);
            accA = fma2(x2, xwA, accA);
            u64 ginB = fma2(x2, winB, binB);
            // phase A: sigmoid, 3 ops: gA = u*(0.5 + CA*u^2) + 0.5
            u64 a2 = mul2(accA, accA);
            u64 qa = fma2(CA, a2, HALF);
            u64 gA = fma2(accA, qa, HALF);
            // hoist the gA shuffle over the phase-B chain
            u64 sAv = __shfl_sync(0xffffffffu, gA, zsrc);
            // phase B: 3 ops with per-lane constants (n: tanh; z: sigmoid)
            u64 rsel = lt20 ? gA : ONE;
            u64 preB = fma2(rsel, accB, ginB);
            u64 b2 = mul2(preB, preB);
            u64 qb = fma2(C3B, b2, A1B);
            u64 gB = fma2(preB, qb, B0B);
            u64 sBv = __shfl_sync(0xffffffffu, gB, zsrc);
            u64 zz = (l < 10) ? sAv : sBv;
            // h' = n + z*(h - n)  (lanes<20; spares compute bounded junk)
            u64 d = add2(h2, neg2(gB));
            h2    = fma2(zz, d, gB);
            // same-warp in-order smem: next step's LDS is ordered after this
            *(u64*)&hbuf[w][tc + 1][l] = h2;
        }

        // y phase: lanes 0..15 = 8 steps x 2 parities; word index
        // (tc+1)*66 + par -> banks 2*tc+2+par, all distinct: conflict-free.
        if (l < 2 * CH) {
            const int tc  = l & (CH - 1);
            const int par = l >> 3;
            const float* hp = &hbuf[w][tc + 1][0].x + par;
            float acc0 = bout_s, acc1 = 0.0f;
#pragma unroll
            for (int k = 0; k < H_ / 2; k++) {
                acc0 = fmaf(wout_s[2 * k],     hp[4 * k],     acc0);
                acc1 = fmaf(wout_s[2 * k + 1], hp[4 * k + 2], acc1);
            }
            out[(bev + par) * T_ + t0 + tc] = acc0 + acc1;
        }
    }

    if (lt20) {
        float lo, hi;
        unpack2(h2, lo, hi);
        out[B_ * T_ + bev * H_ + l]       = lo;
        out[B_ * T_ + (bev + 1) * H_ + l] = hi;
    }
}

extern "C" void kernel_launch(void* const* d_in, const int* in_sizes, int n_in,
                              void* d_out, int out_size) {
    const float* X    = (const float*)d_in[0];
    const float* h0   = (const float*)d_in[1];
    const float* Wih  = (const float*)d_in[2];
    const float* Whh  = (const float*)d_in[3];
    const float* bih  = (const float*)d_in[4];
    const float* bhh  = (const float*)d_in[5];
    const float* Wout = (const float*)d_in[6];
    const float* bout = (const float*)d_in[7];
    float* out = (float*)d_out;
    gru_kernel<<<NBLK, NTH>>>(X, h0, Wih, Whh, bih, bhh, Wout, bout, out);
}

// round 15
// speedup vs baseline: 1.4534x; 1.4534x over previous
#include <cuda_runtime.h>

// GRU: B=2048, T=1024, I=1, H=20.
// d_out layout: [ y (B*T floats, b*T+t) | h_last (B*H floats, b*H+j) ]
//
// R15 = R13 (best: gate-split, 1 pair/warp, 2 warps/SMSP, 53 fma2/step,
// 3-op activations, no loop syncs) + X LDG PREFETCH: chunk c+1's X element
// is loaded into a register at the top of chunk c (in flight across 16
// steps ~ 6700 cyc) and stored to xs after the step loop. This removes the
// per-chunk MLP=1 DRAM/L2 stall (~300-500 cyc x 64 chunks) that both
// co-resident warps hit in phase. Single xs buffer stays safe: same-warp
// in-order LSU puts the STS after chunk c's last xs read and before any
// chunk c+1 read.
// Lane map: l<20: rowA=r_l, rowB=n_l, owns h_l (reg); 20+m: rowA=z_m,
// rowB=z_{m+10}; 30,31 padded. z_j returns via 2 shfl.64 per step.
// sigmoid = 0.5+0.5*tanh (0.5-prescaled weights); 3-op Horner activations.

typedef unsigned long long u64;

#define B_   2048
#define T_   1024
#define H_   20
#define NW   8                 // warps per block (2 per SMSP)
#define PPB  NW                // one pair per warp
#define NTH  (NW * 32)         // 256
#define NBLK (B_ / (2 * PPB))  // 128
#define CH   16
#define NCHUNK (T_ / CH)
#define ROWP 33                // odd row stride (float2) -> conflict-free y-phase

__device__ __forceinline__ u64 pack2(float lo, float hi) {
    u64 r; asm("mov.b64 %0,{%1,%2};" : "=l"(r) : "f"(lo), "f"(hi)); return r;
}
__device__ __forceinline__ u64 dup2(float v) { return pack2(v, v); }
__device__ __forceinline__ void unpack2(u64 a, float& lo, float& hi) {
    asm("mov.b64 {%0,%1},%2;" : "=f"(lo), "=f"(hi) : "l"(a));
}
__device__ __forceinline__ u64 fma2(u64 a, u64 b, u64 c) {
    u64 d; asm("fma.rn.f32x2 %0,%1,%2,%3;" : "=l"(d) : "l"(a), "l"(b), "l"(c)); return d;
}
__device__ __forceinline__ u64 mul2(u64 a, u64 b) {
    u64 d; asm("mul.rn.f32x2 %0,%1,%2;" : "=l"(d) : "l"(a), "l"(b)); return d;
}
__device__ __forceinline__ u64 add2(u64 a, u64 b) {
    u64 d; asm("add.rn.f32x2 %0,%1,%2;" : "=l"(d) : "l"(a), "l"(b)); return d;
}
__device__ __forceinline__ u64 neg2(u64 a) { return a ^ 0x8000000080000000ULL; }

__global__ void __launch_bounds__(NTH, 1)
gru_kernel(const float* __restrict__ X,     // [B, T]
           const float* __restrict__ h0,    // [B, H]
           const float* __restrict__ Wih,   // [3H, 1]
           const float* __restrict__ Whh,   // [3H, H]  rows: r(0..19) z(20..39) n(40..59)
           const float* __restrict__ bih,   // [3H]
           const float* __restrict__ bhh,   // [3H]
           const float* __restrict__ Wout,  // [H]
           const float* __restrict__ bout,  // [1]
           float* __restrict__ out)
{
    __shared__ float2 hbuf[PPB][CH + 1][ROWP];  // per-warp h ring + y history
    __shared__ float2 xs[PPB][CH];              // per-warp packed X chunk
    __shared__ float  wout_s[H_];
    __shared__ float  bout_s;

    const int w    = threadIdx.x >> 5;
    const int l    = threadIdx.x & 31;
    const bool lt20 = (l < 20);
    const bool lt30 = (l < 30);
    const int rowA = l;                            // r_l (l<20) or z_{l-20}
    const int rowB = lt20 ? (40 + l) : (l + 10);   // n_l or z_{l-10}
    const int bev  = (blockIdx.x * PPB + w) * 2;
    // z-gather source lane for unit j=l (<20): j<10 -> lane 20+j (gA),
    // j>=10 -> lane 10+j = 20+(j-10) (gB). Spares: any valid lane.
    const int zsrc = lt20 ? (l < 10 ? 20 + l : 10 + l) : 20;

    // X fetch address for this lane: lane<16 -> even batch, step l;
    // lanes 16..31 -> odd batch, step l-16.
    const int xrow  = (l < CH) ? bev : (bev + 1);
    const int xcol0 = (l < CH) ? l : (l - CH);

    // ---- per-lane packed constants ----
    u64 wA[H_], wB[H_];
#pragma unroll
    for (int k = 0; k < H_; k++) {
        wA[k] = lt30 ? dup2(0.5f * Whh[rowA * H_ + k]) : 0ULL;
        wB[k] = lt30 ? dup2((lt20 ? 1.0f : 0.5f) * Whh[rowB * H_ + k]) : 0ULL;
    }
    const u64 bA0  = lt30 ? dup2(0.5f * (bih[rowA] + bhh[rowA])) : 0ULL;
    const u64 xwA  = lt30 ? dup2(0.5f * Wih[rowA]) : 0ULL;
    const u64 bB0  = lt30 ? (lt20 ? dup2(bhh[rowB])
                                  : dup2(0.5f * (bih[rowB] + bhh[rowB]))) : 0ULL;
    const u64 winB = lt30 ? (lt20 ? dup2(Wih[rowB]) : dup2(0.5f * Wih[rowB])) : 0ULL;
    const u64 binB = (lt30 && lt20) ? dup2(bih[rowB]) : 0ULL;
    const u64 HALF = dup2(0.5f);
    const u64 ONE  = dup2(1.0f);
    // 3-op activation constants
    const u64 CA   = dup2(-1.0f / 6.0f);            // phase A: sigma(2u)
    const u64 C3B  = lt20 ? dup2(-1.0f / 3.0f) : dup2(-1.0f / 6.0f);
    const u64 A1B  = lt20 ? ONE  : HALF;
    const u64 B0B  = lt20 ? 0ULL : HALF;

    // h for owned unit (lanes 0..19) lives in a register
    u64 h2 = lt20 ? pack2(h0[bev * H_ + l], h0[(bev + 1) * H_ + l]) : 0ULL;

    if (threadIdx.x < H_) wout_s[threadIdx.x] = Wout[threadIdx.x];
    if (threadIdx.x == 0) bout_s = bout[0];
    __syncthreads();   // once: publish wout_s/bout_s (cross-warp)

    // prologue: stage chunk 0's X (one element per lane)
    float xreg = X[xrow * T_ + xcol0];
    if (l < CH) xs[w][xcol0].x = xreg;
    else        xs[w][xcol0].y = xreg;

    for (int c = 0; c < NCHUNK; c++) {
        const int t0 = c * CH;
        // prefetch next chunk's X NOW; lands during the 16 steps below.
        const int cn = (c + 1 < NCHUNK) ? (c + 1) : c;   // clamped, deterministic
        float xnext = X[xrow * T_ + cn * CH + xcol0];
        // ring slot 0 (warp-private smem; in-order LSU orders it before the
        // step-0 LDS — no syncwarp needed).
        *(u64*)&hbuf[w][0][l] = h2;

#pragma unroll 8
        for (int tc = 0; tc < CH; tc++) {
            // split even/odd-k accumulators (chain depth 10), LDS.64 reads
            u64 accA0 = bA0, accA1 = 0ULL;
            u64 accB0 = bB0, accB1 = 0ULL;
            const u64* hrow = (const u64*)&hbuf[w][tc][0];
#pragma unroll
            for (int kk = 0; kk < H_ / 2; kk++) {   // 20x LDS.64, 40 fma2
                u64 h0v = hrow[2 * kk];
                u64 h1v = hrow[2 * kk + 1];
                accA0 = fma2(wA[2 * kk],     h0v, accA0);
                accB0 = fma2(wB[2 * kk],     h0v, accB0);
                accA1 = fma2(wA[2 * kk + 1], h1v, accA1);
                accB1 = fma2(wB[2 * kk + 1], h1v, accB1);
            }
            u64 x2 = *(const u64*)&xs[w][tc];
            u64 accA = add2(accA0, accA1);
            u64 accB = add2(accB0, accB1);
            accA = fma2(x2, xwA, accA);
            u64 ginB = fma2(x2, winB, binB);
            // phase A: sigmoid, 3 ops: gA = u*(0.5 + CA*u^2) + 0.5
            u64 a2 = mul2(accA, accA);
            u64 qa = fma2(CA, a2, HALF);
            u64 gA = fma2(accA, qa, HALF);
            // hoist the gA shuffle over the phase-B chain
            u64 sAv = __shfl_sync(0xffffffffu, gA, zsrc);
            // phase B: 3 ops with per-lane constants (n: tanh; z: sigmoid)
            u64 rsel = lt20 ? gA : ONE;
            u64 preB = fma2(rsel, accB, ginB);
            u64 b2 = mul2(preB, preB);
            u64 qb = fma2(C3B, b2, A1B);
            u64 gB = fma2(preB, qb, B0B);
            u64 sBv = __shfl_sync(0xffffffffu, gB, zsrc);
            u64 zz = (l < 10) ? sAv : sBv;
            // h' = n + z*(h - n)  (lanes<20; spares compute bounded junk)
            u64 d = add2(h2, neg2(gB));
            h2    = fma2(zz, d, gB);
            // same-warp in-order smem: next step's LDS is ordered after this
            *(u64*)&hbuf[w][tc + 1][l] = h2;
        }

        // publish next chunk's X: after the last xs read of this chunk,
        // before any read of the next (same-warp in-order LSU).
        if (l < CH) xs[w][xcol0].x = xnext;
        else        xs[w][xcol0].y = xnext;

        // y phase: 32 lanes = 16 steps x 2 parities; odd row stride
        // (66 words, bank step 2) -> conflict-free. 2 chains for latency.
        {
            const int tc  = l & (CH - 1);
            const int par = l >> 4;
            const float* hp = &hbuf[w][tc + 1][0].x + par;
            float acc0 = bout_s, acc1 = 0.0f;
#pragma unroll
            for (int k = 0; k < H_ / 2; k++) {
                acc0 = fmaf(wout_s[2 * k],     hp[4 * k],     acc0);
                acc1 = fmaf(wout_s[2 * k + 1], hp[4 * k + 2], acc1);
            }
            out[(bev + par) * T_ + t0 + tc] = acc0 + acc1;
        }
    }

    if (lt20) {
        float lo, hi;
        unpack2(h2, lo, hi);
        out[B_ * T_ + bev * H_ + l]       = lo;
        out[B_ * T_ + (bev + 1) * H_ + l] = hi;
    }
}

extern "C" void kernel_launch(void* const* d_in, const int* in_sizes, int n_in,
                              void* d_out, int out_size) {
    const float* X    = (const float*)d_in[0];
    const float* h0   = (const float*)d_in[1];
    const float* Wih  = (const float*)d_in[2];
    const float* Whh  = (const float*)d_in[3];
    const float* bih  = (const float*)d_in[4];
    const float* bhh  = (const float*)d_in[5];
    const float* Wout = (const float*)d_in[6];
    const float* bout = (const float*)d_in[7];
    float* out = (float*)d_out;
    gru_kernel<<<NBLK, NTH>>>(X, h0, Wih, Whh, bih, bhh, Wout, bout, out);
}

// round 16
// speedup vs baseline: 1.5420x; 1.0609x over previous
#include <cuda_runtime.h>

// GRU: B=2048, T=1024, I=1, H=20.
// d_out layout: [ y (B*T floats, b*T+t) | h_last (B*H floats, b*H+j) ]
//
// R16 = R15 (gate-split, 1 pair/warp, 2 warps/SMSP, X prefetch, no loop
// syncs) + critical-chain cuts:
//  1) z-branch DECOUPLED from gA: gBz = sigmoid(accB + ginB) computed right
//     after the dot (z-lanes never need r), so its shfl issues ~40 cyc early
//     and the 26-cyc shfl leaves the critical path. n-branch computed
//     separately (preN = gA*accB + ginB, deg-3 tanh); lanes<20 use gBn.
//  2) 4-way split dot accumulators: chain 44 -> 28 cyc (2-level merge).
// Lane map: l<20: rowA=r_l, rowB=n_l, owns h_l (reg); 20+m: rowA=z_m,
// rowB=z_{m+10}; 30,31 padded. sigmoid = 0.5+0.5*tanh(u) with 0.5-prescaled
// weights, deg-3 Horner; n-gate deg-3 tanh. No MUFU. Per-warp smem ring
// (warp-private + convergent -> in-order LSU, no syncwarp). y-phase per CH.

typedef unsigned long long u64;

#define B_   2048
#define T_   1024
#define H_   20
#define NW   8                 // warps per block (2 per SMSP)
#define PPB  NW                // one pair per warp
#define NTH  (NW * 32)         // 256
#define NBLK (B_ / (2 * PPB))  // 128
#define CH   16
#define NCHUNK (T_ / CH)
#define ROWP 33                // odd row stride (float2) -> conflict-free y-phase

__device__ __forceinline__ u64 pack2(float lo, float hi) {
    u64 r; asm("mov.b64 %0,{%1,%2};" : "=l"(r) : "f"(lo), "f"(hi)); return r;
}
__device__ __forceinline__ u64 dup2(float v) { return pack2(v, v); }
__device__ __forceinline__ void unpack2(u64 a, float& lo, float& hi) {
    asm("mov.b64 {%0,%1},%2;" : "=f"(lo), "=f"(hi) : "l"(a));
}
__device__ __forceinline__ u64 fma2(u64 a, u64 b, u64 c) {
    u64 d; asm("fma.rn.f32x2 %0,%1,%2,%3;" : "=l"(d) : "l"(a), "l"(b), "l"(c)); return d;
}
__device__ __forceinline__ u64 mul2(u64 a, u64 b) {
    u64 d; asm("mul.rn.f32x2 %0,%1,%2;" : "=l"(d) : "l"(a), "l"(b)); return d;
}
__device__ __forceinline__ u64 add2(u64 a, u64 b) {
    u64 d; asm("add.rn.f32x2 %0,%1,%2;" : "=l"(d) : "l"(a), "l"(b)); return d;
}
__device__ __forceinline__ u64 neg2(u64 a) { return a ^ 0x8000000080000000ULL; }

__global__ void __launch_bounds__(NTH, 1)
gru_kernel(const float* __restrict__ X,     // [B, T]
           const float* __restrict__ h0,    // [B, H]
           const float* __restrict__ Wih,   // [3H, 1]
           const float* __restrict__ Whh,   // [3H, H]  rows: r(0..19) z(20..39) n(40..59)
           const float* __restrict__ bih,   // [3H]
           const float* __restrict__ bhh,   // [3H]
           const float* __restrict__ Wout,  // [H]
           const float* __restrict__ bout,  // [1]
           float* __restrict__ out)
{
    __shared__ float2 hbuf[PPB][CH + 1][ROWP];  // per-warp h ring + y history
    __shared__ float2 xs[PPB][CH];              // per-warp packed X chunk
    __shared__ float  wout_s[H_];
    __shared__ float  bout_s;

    const int w    = threadIdx.x >> 5;
    const int l    = threadIdx.x & 31;
    const bool lt20 = (l < 20);
    const bool lt30 = (l < 30);
    const int rowA = l;                            // r_l (l<20) or z_{l-20}
    const int rowB = lt20 ? (40 + l) : (l + 10);   // n_l or z_{l-10}
    const int bev  = (blockIdx.x * PPB + w) * 2;
    // z-gather source lane for unit j=l (<20): j<10 -> lane 20+j (gA),
    // j>=10 -> lane 10+j = 20+(j-10) (gBz). Spares: any valid lane.
    const int zsrc = lt20 ? (l < 10 ? 20 + l : 10 + l) : 20;

    // X fetch address for this lane: lane<16 -> even batch, lanes 16..31 odd.
    const int xrow  = (l < CH) ? bev : (bev + 1);
    const int xcol0 = (l < CH) ? l : (l - CH);

    // ---- per-lane packed constants ----
    u64 wA[H_], wB[H_];
#pragma unroll
    for (int k = 0; k < H_; k++) {
        wA[k] = lt30 ? dup2(0.5f * Whh[rowA * H_ + k]) : 0ULL;
        wB[k] = lt30 ? dup2((lt20 ? 1.0f : 0.5f) * Whh[rowB * H_ + k]) : 0ULL;
    }
    const u64 bA0  = lt30 ? dup2(0.5f * (bih[rowA] + bhh[rowA])) : 0ULL;
    const u64 xwA  = lt30 ? dup2(0.5f * Wih[rowA]) : 0ULL;
    const u64 bB0  = lt30 ? (lt20 ? dup2(bhh[rowB])
                                  : dup2(0.5f * (bih[rowB] + bhh[rowB]))) : 0ULL;
    const u64 winB = lt30 ? (lt20 ? dup2(Wih[rowB]) : dup2(0.5f * Wih[rowB])) : 0ULL;
    const u64 binB = (lt30 && lt20) ? dup2(bih[rowB]) : 0ULL;
    const u64 HALF = dup2(0.5f);
    const u64 ONE  = dup2(1.0f);
    const u64 CA   = dup2(-1.0f / 6.0f);   // sigmoid-from-half deg-3 coeff
    const u64 CN   = dup2(-1.0f / 3.0f);   // tanh deg-3 coeff

    // h for owned unit (lanes 0..19) lives in a register
    u64 h2 = lt20 ? pack2(h0[bev * H_ + l], h0[(bev + 1) * H_ + l]) : 0ULL;

    if (threadIdx.x < H_) wout_s[threadIdx.x] = Wout[threadIdx.x];
    if (threadIdx.x == 0) bout_s = bout[0];
    __syncthreads();   // once: publish wout_s/bout_s (cross-warp)

    // prologue: stage chunk 0's X (one element per lane)
    float xreg = X[xrow * T_ + xcol0];
    if (l < CH) xs[w][xcol0].x = xreg;
    else        xs[w][xcol0].y = xreg;

    for (int c = 0; c < NCHUNK; c++) {
        const int t0 = c * CH;
        // prefetch next chunk's X NOW; lands during the 16 steps below.
        const int cn = (c + 1 < NCHUNK) ? (c + 1) : c;   // clamped, deterministic
        float xnext = X[xrow * T_ + cn * CH + xcol0];
        // ring slot 0 (warp-private smem; in-order LSU -> no syncwarp)
        *(u64*)&hbuf[w][0][l] = h2;

#pragma unroll 8
        for (int tc = 0; tc < CH; tc++) {
            // 4-way split accumulators: chain depth 5 + 2-level merge
            u64 accA0 = bA0, accA1 = 0ULL, accA2 = 0ULL, accA3 = 0ULL;
            u64 accB0 = bB0, accB1 = 0ULL, accB2 = 0ULL, accB3 = 0ULL;
            const u64* hrow = (const u64*)&hbuf[w][tc][0];
#pragma unroll
            for (int kk = 0; kk < H_ / 4; kk++) {   // 20x LDS.64, 40 fma2
                u64 h0v = hrow[4 * kk];
                u64 h1v = hrow[4 * kk + 1];
                u64 h2v = hrow[4 * kk + 2];
                u64 h3v = hrow[4 * kk + 3];
                accA0 = fma2(wA[4 * kk],     h0v, accA0);
                accB0 = fma2(wB[4 * kk],     h0v, accB0);
                accA1 = fma2(wA[4 * kk + 1], h1v, accA1);
                accB1 = fma2(wB[4 * kk + 1], h1v, accB1);
                accA2 = fma2(wA[4 * kk + 2], h2v, accA2);
                accB2 = fma2(wB[4 * kk + 2], h2v, accB2);
                accA3 = fma2(wA[4 * kk + 3], h3v, accA3);
                accB3 = fma2(wB[4 * kk + 3], h3v, accB3);
            }
            u64 x2 = *(const u64*)&xs[w][tc];
            u64 accB = add2(add2(accB0, accB1), add2(accB2, accB3));
            u64 ginB = fma2(x2, winB, binB);
            // EARLY z-branch: sigmoid(accB + ginB), no gA dependency ->
            // its shfl issues ~40 cyc before the n-chain finishes.
            u64 preZ = add2(accB, ginB);
            u64 z2v  = mul2(preZ, preZ);
            u64 qz   = fma2(CA, z2v, HALF);
            u64 gBz  = fma2(preZ, qz, HALF);
            u64 sBv  = __shfl_sync(0xffffffffu, gBz, zsrc);
            // phase A: sigmoid (r on lanes<20, z_m on 20..29)
            u64 accA = add2(add2(accA0, accA1), add2(accA2, accA3));
            accA = fma2(x2, xwA, accA);
            u64 a2 = mul2(accA, accA);
            u64 qa = fma2(CA, a2, HALF);
            u64 gA = fma2(accA, qa, HALF);
            u64 sAv = __shfl_sync(0xffffffffu, gA, zsrc);
            // n-branch (lanes<20): preN = r*accB + ginB; deg-3 tanh
            u64 preN = fma2(gA, accB, ginB);
            u64 n2 = mul2(preN, preN);
            u64 qn = fma2(CN, n2, ONE);
            u64 gBn = mul2(preN, qn);
            // h' = n + z*(h - n); zz ready (both shfls overlapped)
            u64 zz = (l < 10) ? sAv : sBv;
            u64 d = add2(h2, neg2(gBn));
            h2    = fma2(zz, d, gBn);
            // same-warp in-order smem: next step's LDS ordered after this
            *(u64*)&hbuf[w][tc + 1][l] = h2;
        }

        // publish next chunk's X (after this chunk's last xs read)
        if (l < CH) xs[w][xcol0].x = xnext;
        else        xs[w][xcol0].y = xnext;

        // y phase: 32 lanes = 16 steps x 2 parities; odd row stride
        // (66 words, bank step 2) -> conflict-free. 2 chains for latency.
        {
            const int tc  = l & (CH - 1);
            const int par = l >> 4;
            const float* hp = &hbuf[w][tc + 1][0].x + par;
            float acc0 = bout_s, acc1 = 0.0f;
#pragma unroll
            for (int k = 0; k < H_ / 2; k++) {
                acc0 = fmaf(wout_s[2 * k],     hp[4 * k],     acc0);
                acc1 = fmaf(wout_s[2 * k + 1], hp[4 * k + 2], acc1);
            }
            out[(bev + par) * T_ + t0 + tc] = acc0 + acc1;
        }
    }

    if (lt20) {
        float lo, hi;
        unpack2(h2, lo, hi);
        out[B_ * T_ + bev * H_ + l]       = lo;
        out[B_ * T_ + (bev + 1) * H_ + l] = hi;
    }
}

extern "C" void kernel_launch(void* const* d_in, const int* in_sizes, int n_in,
                              void* d_out, int out_size) {
    const float* X    = (const float*)d_in[0];
    const float* h0   = (const float*)d_in[1];
    const float* Wih  = (const float*)d_in[2];
    const float* Whh  = (const float*)d_in[3];
    const float* bih  = (const float*)d_in[4];
    const float* bhh  = (const float*)d_in[5];
    const float* Wout = (const float*)d_in[6];
    const float* bout = (const float*)d_in[7];
    float* out = (float*)d_out;
    gru_kernel<<<NBLK, NTH>>>(X, h0, Wih, Whh, bih, bhh, Wout, bout, out);
}